// round 2
// baseline (speedup 1.0000x reference)
#include <cuda_runtime.h>
#include <cuda_bf16.h>
#include <cstddef>

// Problem constants
#define V    4096
#define D    128
#define KS   3
#define NH   4
#define HD   32
#define FF   128
#define NL   2
#define NVIS 8192
#define MAXC 32

// ---------------- scratch (device globals; no allocation allowed) ----------
__device__ float g_Z0[V * D];          // logmap0 output
__device__ float g_Y[KS * V * D];      // Yk = Z0 @ Wk^T
__device__ float g_X[V * D];           // current hidden state
__device__ float g_qkv[V * 3 * D];     // qkv projections
__device__ float g_attn[V * D];        // attention output (pre-Wo)
__device__ float g_tmp[V * D];         // pre-layernorm residual sum
__device__ float g_ff[V * FF];         // ff hidden

// ---------------- logmap0 ---------------------------------------------------
__global__ void k_logmap0(const float* __restrict__ X, float* __restrict__ Z) {
    __shared__ float red[128];
    int row = blockIdx.x, d = threadIdx.x;
    float x = X[row * D + d];
    red[d] = x * x;
    __syncthreads();
    for (int s = 64; s > 0; s >>= 1) {
        if (d < s) red[d] += red[d + s];
        __syncthreads();
    }
    float norm = sqrtf(red[0]);
    float nc = fminf(fmaxf(norm, 1e-7f), 1.0f - 1e-5f);
    float at = 0.5f * logf((1.0f + nc) / (1.0f - nc));  // artanh
    float sc = at / fmaxf(norm, 1e-7f);
    Z[row * D + d] = sc * x;
}

// ---------------- generic tiled fp32 GEMM ----------------------------------
// C[m,n] = sum_k A[m,k]*B[k,n]  (+bias[n]) (+residual[m,n]) (optional gelu)
// A addressed via (rsA, csA); B via (rsB, csB); C row-major with ld = N.
// Requires M%64==0, N%64==0, Kdim%32==0 (true for all uses here).
#define BM 64
#define BN 64
#define BK 32

__global__ __launch_bounds__(256) void k_gemm(
    const float* __restrict__ A, int rsA, int csA,
    const float* __restrict__ B, int rsB, int csB,
    float* __restrict__ C, int N, int Kdim,
    const float* __restrict__ bias,
    const float* __restrict__ residual,
    int gelu_flag)
{
    __shared__ float As[BK][BM + 4];
    __shared__ float Bs[BK][BN + 4];

    int tid = threadIdx.x;            // 256 threads
    int tx = tid & 15, ty = tid >> 4; // 16x16 thread grid, 4x4 micro-tile
    int m0 = blockIdx.y * BM;
    int n0 = blockIdx.x * BN;

    float acc[4][4] = {};

    for (int k0 = 0; k0 < Kdim; k0 += BK) {
        // load A tile (kk fastest => contiguous when csA==1)
        #pragma unroll
        for (int i = 0; i < 8; i++) {
            int idx = tid + i * 256;
            int kk = idx & (BK - 1);
            int m  = idx >> 5;
            As[kk][m] = A[(size_t)(m0 + m) * rsA + (size_t)(k0 + kk) * csA];
        }
        // load B tile
        if (csB == 1) {
            #pragma unroll
            for (int i = 0; i < 8; i++) {
                int idx = tid + i * 256;
                int n  = idx & (BN - 1);
                int kk = idx >> 6;
                Bs[kk][n] = B[(size_t)(k0 + kk) * rsB + (size_t)(n0 + n)];
            }
        } else {
            #pragma unroll
            for (int i = 0; i < 8; i++) {
                int idx = tid + i * 256;
                int kk = idx & (BK - 1);
                int n  = idx >> 5;
                Bs[kk][n] = B[(size_t)(k0 + kk) * rsB + (size_t)(n0 + n) * csB];
            }
        }
        __syncthreads();

        #pragma unroll
        for (int kk = 0; kk < BK; kk++) {
            float4 a4 = *(const float4*)&As[kk][ty * 4];
            float4 b4 = *(const float4*)&Bs[kk][tx * 4];
            float av[4] = {a4.x, a4.y, a4.z, a4.w};
            float bv[4] = {b4.x, b4.y, b4.z, b4.w};
            #pragma unroll
            for (int i = 0; i < 4; i++)
                #pragma unroll
                for (int j = 0; j < 4; j++)
                    acc[i][j] += av[i] * bv[j];
        }
        __syncthreads();
    }

    #pragma unroll
    for (int i = 0; i < 4; i++) {
        int m = m0 + ty * 4 + i;
        #pragma unroll
        for (int j = 0; j < 4; j++) {
            int n = n0 + tx * 4 + j;
            float v = acc[i][j];
            if (bias) v += bias[n];
            if (residual) v += residual[(size_t)m * N + n];
            if (gelu_flag) {
                float x = v;
                float t = tanhf(0.7978845608028654f * (x + 0.044715f * x * x * x));
                v = 0.5f * x * (1.0f + t);
            }
            C[(size_t)m * N + n] = v;
        }
    }
}

// ---------------- flash attention (hd=32, H=4, V=4096) ---------------------
// one thread per (query, head); online softmax; K/V tiles staged in smem.
__global__ __launch_bounds__(128) void k_attn(const float* __restrict__ qkv,
                                              float* __restrict__ O)
{
    __shared__ float Ksm[128][HD];
    __shared__ float Vsm[128][HD];

    int h = blockIdx.y;
    int q = blockIdx.x * 128 + threadIdx.x;
    int warp = threadIdx.x >> 5, lane = threadIdx.x & 31;
    const float scale = 0.17677669529663687f;  // 1/sqrt(32)

    float qv[HD];
    const float* qp = qkv + (size_t)q * 3 * D + h * HD;
    #pragma unroll
    for (int e = 0; e < HD; e++) qv[e] = qp[e];

    float m = -1e30f, l = 0.0f;
    float o[HD];
    #pragma unroll
    for (int e = 0; e < HD; e++) o[e] = 0.0f;

    for (int t0 = 0; t0 < V; t0 += 128) {
        __syncthreads();
        // each warp loads 32 rows; lane = element index (coalesced 128B/row)
        #pragma unroll 4
        for (int r = 0; r < 32; r++) {
            int row = warp * 32 + r;
            size_t base = (size_t)(t0 + row) * (3 * D) + h * HD + lane;
            Ksm[row][lane] = qkv[base + D];
            Vsm[row][lane] = qkv[base + 2 * D];
        }
        __syncthreads();

        for (int t = 0; t < 128; t++) {
            const float4* kp = (const float4*)Ksm[t];
            float s = 0.0f;
            #pragma unroll
            for (int e4 = 0; e4 < 8; e4++) {
                float4 kk = kp[e4];
                s += qv[4 * e4 + 0] * kk.x + qv[4 * e4 + 1] * kk.y +
                     qv[4 * e4 + 2] * kk.z + qv[4 * e4 + 3] * kk.w;
            }
            s *= scale;
            if (s > m) {
                float c = __expf(m - s);
                l *= c;
                #pragma unroll
                for (int e = 0; e < HD; e++) o[e] *= c;
                m = s;
            }
            float p = __expf(s - m);
            l += p;
            const float4* vp = (const float4*)Vsm[t];
            #pragma unroll
            for (int e4 = 0; e4 < 8; e4++) {
                float4 vv = vp[e4];
                o[4 * e4 + 0] += p * vv.x;
                o[4 * e4 + 1] += p * vv.y;
                o[4 * e4 + 2] += p * vv.z;
                o[4 * e4 + 3] += p * vv.w;
            }
        }
    }

    float inv = 1.0f / l;
    float* op = O + (size_t)q * D + h * HD;
    #pragma unroll
    for (int e = 0; e < HD; e++) op[e] = o[e] * inv;
}

// ---------------- layernorm (per row of 128) --------------------------------
__global__ void k_ln(const float* __restrict__ in, const float* __restrict__ g,
                     const float* __restrict__ b, float* __restrict__ out)
{
    __shared__ float red[128];
    int row = blockIdx.x, d = threadIdx.x;
    float x = in[row * D + d];
    red[d] = x;
    __syncthreads();
    for (int s = 64; s > 0; s >>= 1) {
        if (d < s) red[d] += red[d + s];
        __syncthreads();
    }
    float mean = red[0] * (1.0f / 128.0f);
    __syncthreads();
    float c = x - mean;
    red[d] = c * c;
    __syncthreads();
    for (int s = 64; s > 0; s >>= 1) {
        if (d < s) red[d] += red[d + s];
        __syncthreads();
    }
    float var = red[0] * (1.0f / 128.0f);
    out[row * D + d] = c * rsqrtf(var + 1e-5f) * g[d] + b[d];
}

// ---------------- per-visit masked mean pooling ------------------------------
__global__ void k_pool(const int* __restrict__ visits,
                       const float* __restrict__ Xf, float* __restrict__ out)
{
    int vis = blockIdx.x, d = threadIdx.x;
    float s = 0.0f;
    int cnt = 0;
    #pragma unroll 8
    for (int c = 0; c < MAXC; c++) {
        int code = visits[vis * MAXC + c];
        if (code != 0) {
            cnt++;
            s += Xf[(size_t)code * D + d];
        }
    }
    out[(size_t)vis * D + d] = (cnt > 0) ? (s / (float)cnt) : 0.0f;
}

// ---------------- host orchestration ----------------------------------------
extern "C" void kernel_launch(void* const* d_in, const int* in_sizes, int n_in,
                              void* d_out, int out_size)
{
    const int*   visits  = (const int*)d_in[0];
    const float* X_hyp   = (const float*)d_in[1];
    const float* kernels = (const float*)d_in[2];
    const float* proj_W  = (const float*)d_in[3];
    const float* proj_b  = (const float*)d_in[4];
    const float* Wqkv    = (const float*)d_in[5];
    const float* bqkv    = (const float*)d_in[6];
    const float* Wo      = (const float*)d_in[7];
    const float* bo      = (const float*)d_in[8];
    const float* W1      = (const float*)d_in[9];
    const float* b1      = (const float*)d_in[10];
    const float* W2      = (const float*)d_in[11];
    const float* b2      = (const float*)d_in[12];
    const float* ln1_g   = (const float*)d_in[13];
    const float* ln1_b   = (const float*)d_in[14];
    const float* ln2_g   = (const float*)d_in[15];
    const float* ln2_b   = (const float*)d_in[16];
    float* out = (float*)d_out;

    float *pZ0, *pY, *pX, *pqkv, *pattn, *ptmp, *pff;
    cudaGetSymbolAddress((void**)&pZ0,   g_Z0);
    cudaGetSymbolAddress((void**)&pY,    g_Y);
    cudaGetSymbolAddress((void**)&pX,    g_X);
    cudaGetSymbolAddress((void**)&pqkv,  g_qkv);
    cudaGetSymbolAddress((void**)&pattn, g_attn);
    cudaGetSymbolAddress((void**)&ptmp,  g_tmp);
    cudaGetSymbolAddress((void**)&pff,   g_ff);

    // 1) logmap0
    k_logmap0<<<V, 128>>>(X_hyp, pZ0);

    // 2) Yk = Z0 @ Wk^T  (Wk = proj_W[:, k*D:(k+1)*D], proj_W is [D, 3D])
    for (int k = 0; k < KS; k++) {
        k_gemm<<<dim3(D / BN, V / BM), 256>>>(
            pZ0, D, 1,
            proj_W + k * D, 1, KS * D,
            pY + (size_t)k * V * D, D, D,
            nullptr, nullptr, 0);
    }

    // 3) X = proj_b + sum_k kernels[k] @ Yk
    for (int k = 0; k < KS; k++) {
        k_gemm<<<dim3(D / BN, V / BM), 256>>>(
            kernels + (size_t)k * V * V, V, 1,
            pY + (size_t)k * V * D, D, 1,
            pX, D, V,
            (k == 0) ? proj_b : nullptr,
            (k == 0) ? nullptr : pX, 0);
    }

    // 4) transformer layers
    for (int l = 0; l < NL; l++) {
        // qkv = X @ Wqkv^T + bqkv
        k_gemm<<<dim3((3 * D) / BN, V / BM), 256>>>(
            pX, D, 1,
            Wqkv + (size_t)l * 3 * D * D, 1, D,
            pqkv, 3 * D, D,
            bqkv + l * 3 * D, nullptr, 0);

        // attention -> g_attn
        k_attn<<<dim3(V / 128, NH), 128>>>(pqkv, pattn);

        // tmp = X + attn @ Wo^T + bo
        k_gemm<<<dim3(D / BN, V / BM), 256>>>(
            pattn, D, 1,
            Wo + (size_t)l * D * D, 1, D,
            ptmp, D, D,
            bo + l * D, pX, 0);

        // X = LN1(tmp)
        k_ln<<<V, 128>>>(ptmp, ln1_g + l * D, ln1_b + l * D, pX);

        // ff = gelu(X @ W1^T + b1)
        k_gemm<<<dim3(FF / BN, V / BM), 256>>>(
            pX, D, 1,
            W1 + (size_t)l * FF * D, 1, D,
            pff, FF, D,
            b1 + l * FF, nullptr, 1);

        // tmp = X + ff @ W2^T + b2
        k_gemm<<<dim3(D / BN, V / BM), 256>>>(
            pff, FF, 1,
            W2 + (size_t)l * D * FF, 1, FF,
            ptmp, D, FF,
            b2 + l * D, pX, 0);

        // X = LN2(tmp)
        k_ln<<<V, 128>>>(ptmp, ln2_g + l * D, ln2_b + l * D, pX);
    }

    // 5) pooling
    k_pool<<<NVIS, 128>>>(visits, pX, out);
}

// round 5
// speedup vs baseline: 2.3702x; 2.3702x over previous
#include <cuda_runtime.h>
#include <cuda_bf16.h>
#include <cstdint>
#include <cstddef>

#define V    4096
#define D    128
#define KS   3
#define NH   4
#define HD   32
#define FF   128
#define NL   2
#define NVIS 8192
#define MAXC 32

// ===================== scratch ==============================================
__device__ float g_Z0[V * D];
__device__ float g_Yt[KS * D * V];
__device__ __nv_bfloat16 g_Z0h[V * D], g_Z0l[V * D];
__device__ __nv_bfloat16 g_pWh[D * KS * D], g_pWl[D * KS * D];
__device__ __nv_bfloat16 g_Yth[KS * D * V], g_Ytl[KS * D * V];
__device__ __nv_bfloat16 g_Kh[KS * V * V], g_Kl[KS * V * V];
__device__ float g_part[12 * V * D];
__device__ float g_X[V * D], g_qkv[V * 3 * D], g_attn[V * D], g_tmp[V * D], g_ff[V * FF];
__device__ __nv_bfloat16 g_sh[V * D], g_sl[V * D];        // activation splits
__device__ __nv_bfloat16 g_wh[3 * D * D], g_wl[3 * D * D]; // weight splits
__device__ float g_opart[NH * 8 * V * HD];
__device__ float g_lpart[NH * 8 * V];

// ===================== helpers ==============================================
__device__ __forceinline__ uint32_t smem_u32(const void* p) {
    uint32_t a;
    asm("{ .reg .u64 t; cvta.to.shared.u64 t, %1; cvt.u32.u64 %0, t; }" : "=r"(a) : "l"(p));
    return a;
}
__device__ __forceinline__ void mma_bf16(float* c, const uint32_t* a, const uint32_t* b) {
    asm volatile("mma.sync.aligned.m16n8k16.row.col.f32.bf16.bf16.f32 "
        "{%0,%1,%2,%3},{%4,%5,%6,%7},{%8,%9},{%0,%1,%2,%3};"
        : "+f"(c[0]), "+f"(c[1]), "+f"(c[2]), "+f"(c[3])
        : "r"(a[0]), "r"(a[1]), "r"(a[2]), "r"(a[3]), "r"(b[0]), "r"(b[1]));
}
__device__ __forceinline__ void ldsm4(uint32_t* r, uint32_t addr) {
    asm volatile("ldmatrix.sync.aligned.m8n8.x4.shared.b16 {%0,%1,%2,%3}, [%4];"
        : "=r"(r[0]), "=r"(r[1]), "=r"(r[2]), "=r"(r[3]) : "r"(addr));
}
__device__ __forceinline__ float gelu_f(float x) {
    float t = tanhf(0.7978845608028654f * (x + 0.044715f * x * x * x));
    return 0.5f * x * (1.0f + t);
}

// ===================== elementwise kernels ==================================
__global__ void k_logmap0(const float* __restrict__ X, float* __restrict__ Z) {
    __shared__ float red[128];
    int row = blockIdx.x, d = threadIdx.x;
    float x = X[row * D + d];
    red[d] = x * x;
    __syncthreads();
    for (int s = 64; s > 0; s >>= 1) { if (d < s) red[d] += red[d + s]; __syncthreads(); }
    float norm = sqrtf(red[0]);
    float nc = fminf(fmaxf(norm, 1e-7f), 1.0f - 1e-5f);
    float at = 0.5f * logf((1.0f + nc) / (1.0f - nc));
    Z[row * D + d] = (at / fmaxf(norm, 1e-7f)) * x;
}

__global__ void k_split(const float* __restrict__ in, __nv_bfloat16* __restrict__ hi,
                        __nv_bfloat16* __restrict__ lo, long n4) {
    long i = (long)blockIdx.x * blockDim.x + threadIdx.x;
    if (i >= n4) return;
    float4 v = ((const float4*)in)[i];
    float f[4] = {v.x, v.y, v.z, v.w};
    uint32_t hw[2] = {0, 0}, lw[2] = {0, 0};
    #pragma unroll
    for (int j = 0; j < 4; j++) {
        __nv_bfloat16 h = __float2bfloat16(f[j]);
        __nv_bfloat16 l = __float2bfloat16(f[j] - __bfloat162float(h));
        hw[j >> 1] |= (uint32_t)__bfloat16_as_ushort(h) << ((j & 1) * 16);
        lw[j >> 1] |= (uint32_t)__bfloat16_as_ushort(l) << ((j & 1) * 16);
    }
    ((uint2*)hi)[i] = make_uint2(hw[0], hw[1]);
    ((uint2*)lo)[i] = make_uint2(lw[0], lw[1]);
}

__global__ void k_reduce12(const float* __restrict__ part, const float* __restrict__ bias,
                           float* __restrict__ X) {
    int m = blockIdx.x, d = threadIdx.x;
    float s = bias[d];
    #pragma unroll
    for (int i = 0; i < 12; i++) s += part[((size_t)i * V + m) * D + d];
    X[m * D + d] = s;
}

__global__ void k_ln(const float* __restrict__ in, const float* __restrict__ g,
                     const float* __restrict__ b, float* __restrict__ out) {
    __shared__ float red[128];
    int row = blockIdx.x, d = threadIdx.x;
    float x = in[row * D + d];
    red[d] = x;
    __syncthreads();
    for (int s = 64; s > 0; s >>= 1) { if (d < s) red[d] += red[d + s]; __syncthreads(); }
    float mean = red[0] * (1.0f / 128.0f);
    __syncthreads();
    float c = x - mean;
    red[d] = c * c;
    __syncthreads();
    for (int s = 64; s > 0; s >>= 1) { if (d < s) red[d] += red[d + s]; __syncthreads(); }
    float var = red[0] * (1.0f / 128.0f);
    out[row * D + d] = c * rsqrtf(var + 1e-5f) * g[d] + b[d];
}

__global__ void k_pool(const int* __restrict__ visits, const float* __restrict__ Xf,
                       float* __restrict__ out) {
    int vis = blockIdx.x, d = threadIdx.x;
    float s = 0.0f;
    int cnt = 0;
    #pragma unroll 8
    for (int c = 0; c < MAXC; c++) {
        int code = visits[vis * MAXC + c];
        if (code != 0) { cnt++; s += Xf[(size_t)code * D + d]; }
    }
    out[(size_t)vis * D + d] = (cnt > 0) ? (s / (float)cnt) : 0.0f;
}

// ===================== generic HMMA GEMM ====================================
// C[M,N] = A[M,K] @ W[N,K]^T in bf16 hi/lo 3-pass; 128x128 tile per CTA.
// z -> (s = z/ksplit batch offset, j = z%ksplit K-range); K-chunk = 32.
__global__ __launch_bounds__(256) void k_mm(
    const __nv_bfloat16* __restrict__ Ah, const __nv_bfloat16* __restrict__ Al, int lda, long sA,
    const __nv_bfloat16* __restrict__ Wh, const __nv_bfloat16* __restrict__ Wl, int ldw, long sW,
    float* __restrict__ C, int ldc, long sC,
    int ksplit, int ksub,
    const float* __restrict__ bias, const float* __restrict__ resid, int gelu)
{
    __shared__ __align__(16) char sm[4][128 * 80];
    int tid = threadIdx.x, lane = tid & 31, wid = tid >> 5;
    int z = blockIdx.z, s = z / ksplit, j = z - s * ksplit;
    Ah += (long)s * sA; Al += (long)s * sA;
    Wh += (long)s * sW; Wl += (long)s * sW;
    C += (long)z * sC;
    int m0 = blockIdx.x * 128, n0 = blockIdx.y * 128, k0 = j * ksub;
    int wm = wid & 3, wn = wid >> 2, mb = wm * 32, nb = wn * 64;
    int g = lane >> 2, tg = lane & 3;
    int l8 = lane & 7, q4 = lane >> 3;
    int a_ro = ((q4 & 1) << 3) + l8, a_co = (q4 >> 1) << 3;
    int b_ro = ((q4 >> 1) << 3) + l8, b_co = (q4 & 1) << 3;
    uint32_t smb = smem_u32(sm);

    float acc[2][8][4];
    #pragma unroll
    for (int a = 0; a < 2; a++)
        #pragma unroll
        for (int b = 0; b < 8; b++)
            #pragma unroll
            for (int c = 0; c < 4; c++) acc[a][b][c] = 0.0f;

    for (int c0 = k0; c0 < k0 + ksub; c0 += 32) {
        __syncthreads();
        #pragma unroll
        for (int i = 0; i < 8; i++) {
            int idx = tid + i * 256;
            int buf = idx >> 9, r = (idx >> 2) & 127, q = idx & 3;
            const __nv_bfloat16* src = (buf == 0) ? Ah : (buf == 1) ? Al : (buf == 2) ? Wh : Wl;
            int ld = (buf < 2) ? lda : ldw;
            int rb = (buf < 2) ? m0 : n0;
            *(uint4*)(sm[buf] + r * 80 + q * 16) =
                *(const uint4*)(src + (size_t)(rb + r) * ld + c0 + q * 8);
        }
        __syncthreads();
        #pragma unroll
        for (int kk = 0; kk < 32; kk += 16) {
            uint32_t ah[2][4], al[2][4], bh[8][2], bl[8][2], t[4];
            #pragma unroll
            for (int mf = 0; mf < 2; mf++) {
                uint32_t ad = smb + (mb + mf * 16 + a_ro) * 80 + (kk + a_co) * 2;
                ldsm4(ah[mf], ad);
                ldsm4(al[mf], ad + 10240);
            }
            #pragma unroll
            for (int nf2 = 0; nf2 < 4; nf2++) {
                uint32_t bd = smb + 2 * 10240 + (nb + nf2 * 16 + b_ro) * 80 + (kk + b_co) * 2;
                ldsm4(t, bd);
                bh[2*nf2][0] = t[0]; bh[2*nf2][1] = t[1];
                bh[2*nf2+1][0] = t[2]; bh[2*nf2+1][1] = t[3];
                ldsm4(t, bd + 10240);
                bl[2*nf2][0] = t[0]; bl[2*nf2][1] = t[1];
                bl[2*nf2+1][0] = t[2]; bl[2*nf2+1][1] = t[3];
            }
            #pragma unroll
            for (int mf = 0; mf < 2; mf++)
                #pragma unroll
                for (int nf = 0; nf < 8; nf++) {
                    mma_bf16(acc[mf][nf], ah[mf], bh[nf]);
                    mma_bf16(acc[mf][nf], al[mf], bh[nf]);
                    mma_bf16(acc[mf][nf], ah[mf], bl[nf]);
                }
        }
    }

    #pragma unroll
    for (int mf = 0; mf < 2; mf++)
        #pragma unroll
        for (int nf = 0; nf < 8; nf++) {
            int m = m0 + mb + mf * 16 + g;
            int n = n0 + nb + nf * 8 + tg * 2;
            float v0 = acc[mf][nf][0], v1 = acc[mf][nf][1];
            float v2 = acc[mf][nf][2], v3 = acc[mf][nf][3];
            if (bias) {
                float b0 = bias[n], b1 = bias[n + 1];
                v0 += b0; v1 += b1; v2 += b0; v3 += b1;
            }
            if (resid) {
                float2 r0 = *(const float2*)&resid[(size_t)m * ldc + n];
                float2 r1 = *(const float2*)&resid[(size_t)(m + 8) * ldc + n];
                v0 += r0.x; v1 += r0.y; v2 += r1.x; v3 += r1.y;
            }
            if (gelu) { v0 = gelu_f(v0); v1 = gelu_f(v1); v2 = gelu_f(v2); v3 = gelu_f(v3); }
            *(float2*)&C[(size_t)m * ldc + n] = make_float2(v0, v1);
            *(float2*)&C[(size_t)(m + 8) * ldc + n] = make_float2(v2, v3);
        }
}

// ===================== attention (SIMT, 8-way key split) ====================
__global__ __launch_bounds__(128) void k_attn_part(
    const float* __restrict__ qkv, float* __restrict__ op, float* __restrict__ lp)
{
    __shared__ float Ksm[128][HD];
    __shared__ float Vsm[128][HD];
    int h = blockIdx.y, q = blockIdx.x * 128 + threadIdx.x;
    int warp = threadIdx.x >> 5, lane = threadIdx.x & 31;
    int ks0 = blockIdx.z * 512;
    const float scale = 0.17677669529663687f;

    float qv[HD];
    const float* qp = qkv + (size_t)q * 384 + h * HD;
    #pragma unroll
    for (int e = 0; e < HD; e++) qv[e] = qp[e] * scale;

    float o[HD];
    #pragma unroll
    for (int e = 0; e < HD; e++) o[e] = 0.0f;
    float l = 0.0f;

    for (int t0 = ks0; t0 < ks0 + 512; t0 += 128) {
        __syncthreads();
        #pragma unroll 4
        for (int r = 0; r < 32; r++) {
            int row = warp * 32 + r;
            size_t base = (size_t)(t0 + row) * 384 + h * HD + lane;
            Ksm[row][lane] = qkv[base + 128];
            Vsm[row][lane] = qkv[base + 256];
        }
        __syncthreads();
        for (int t = 0; t < 128; t++) {
            const float4* kp = (const float4*)Ksm[t];
            float s = 0.0f;
            #pragma unroll
            for (int e4 = 0; e4 < 8; e4++) {
                float4 kk = kp[e4];
                s += qv[4*e4] * kk.x + qv[4*e4+1] * kk.y + qv[4*e4+2] * kk.z + qv[4*e4+3] * kk.w;
            }
            float e = __expf(s);
            l += e;
            const float4* vp = (const float4*)Vsm[t];
            #pragma unroll
            for (int e4 = 0; e4 < 8; e4++) {
                float4 vv = vp[e4];
                o[4*e4] += e * vv.x; o[4*e4+1] += e * vv.y;
                o[4*e4+2] += e * vv.z; o[4*e4+3] += e * vv.w;
            }
        }
    }
    float* od = op + (((size_t)h * 8 + blockIdx.z) * V + q) * HD;
    #pragma unroll
    for (int e = 0; e < HD; e++) od[e] = o[e];
    lp[((size_t)h * 8 + blockIdx.z) * V + q] = l;
}

__global__ void k_comb(const float* __restrict__ op, const float* __restrict__ lp,
                       float* __restrict__ attn) {
    int q = blockIdx.x, tid = threadIdx.x;
    int h = tid >> 5, d = tid & 31;
    float os = 0.0f, ls = 0.0f;
    #pragma unroll
    for (int s = 0; s < 8; s++) {
        os += op[(((size_t)h * 8 + s) * V + q) * HD + d];
        ls += lp[((size_t)h * 8 + s) * V + q];
    }
    attn[(size_t)q * D + h * HD + d] = os / ls;
}

// ===================== host orchestration ===================================
extern "C" void kernel_launch(void* const* d_in, const int* in_sizes, int n_in,
                              void* d_out, int out_size)
{
    const int*   visits  = (const int*)d_in[0];
    const float* X_hyp   = (const float*)d_in[1];
    const float* kernels = (const float*)d_in[2];
    const float* proj_W  = (const float*)d_in[3];
    const float* proj_b  = (const float*)d_in[4];
    const float* Wqkv    = (const float*)d_in[5];
    const float* bqkv    = (const float*)d_in[6];
    const float* Wo      = (const float*)d_in[7];
    const float* bo      = (const float*)d_in[8];
    const float* W1      = (const float*)d_in[9];
    const float* b1      = (const float*)d_in[10];
    const float* W2      = (const float*)d_in[11];
    const float* b2      = (const float*)d_in[12];
    const float* ln1_g   = (const float*)d_in[13];
    const float* ln1_b   = (const float*)d_in[14];
    const float* ln2_g   = (const float*)d_in[15];
    const float* ln2_b   = (const float*)d_in[16];
    float* out = (float*)d_out;

    float *pZ0, *pYt, *pPart, *pX, *pqkv, *pattn, *ptmp, *pff, *pop, *plp;
    __nv_bfloat16 *pZ0h, *pZ0l, *ppWh, *ppWl, *pYth, *pYtl, *pKh, *pKl, *psh, *psl, *pwh, *pwl;
    cudaGetSymbolAddress((void**)&pZ0, g_Z0);
    cudaGetSymbolAddress((void**)&pYt, g_Yt);
    cudaGetSymbolAddress((void**)&pPart, g_part);
    cudaGetSymbolAddress((void**)&pX, g_X);
    cudaGetSymbolAddress((void**)&pqkv, g_qkv);
    cudaGetSymbolAddress((void**)&pattn, g_attn);
    cudaGetSymbolAddress((void**)&ptmp, g_tmp);
    cudaGetSymbolAddress((void**)&pff, g_ff);
    cudaGetSymbolAddress((void**)&pop, g_opart);
    cudaGetSymbolAddress((void**)&plp, g_lpart);
    cudaGetSymbolAddress((void**)&pZ0h, g_Z0h);
    cudaGetSymbolAddress((void**)&pZ0l, g_Z0l);
    cudaGetSymbolAddress((void**)&ppWh, g_pWh);
    cudaGetSymbolAddress((void**)&ppWl, g_pWl);
    cudaGetSymbolAddress((void**)&pYth, g_Yth);
    cudaGetSymbolAddress((void**)&pYtl, g_Ytl);
    cudaGetSymbolAddress((void**)&pKh, g_Kh);
    cudaGetSymbolAddress((void**)&pKl, g_Kl);
    cudaGetSymbolAddress((void**)&psh, g_sh);
    cudaGetSymbolAddress((void**)&psl, g_sl);
    cudaGetSymbolAddress((void**)&pwh, g_wh);
    cudaGetSymbolAddress((void**)&pwl, g_wl);

    auto split = [&](const float* src, __nv_bfloat16* h, __nv_bfloat16* l, long n) {
        long n4 = n / 4;
        k_split<<<(unsigned)((n4 + 255) / 256), 256>>>(src, h, l, n4);
    };

    // 1) logmap0 + splits
    k_logmap0<<<V, 128>>>(X_hyp, pZ0);
    split(pZ0, pZ0h, pZ0l, (long)V * D);
    split(proj_W, ppWh, ppWl, (long)D * KS * D);

    // 2) Yt[s][n][v] = sum_d proj_W[n, s*128+d] * Z0[v, d]   (M=128, N=V, K=128)
    k_mm<<<dim3(1, 32, 3), 256>>>(ppWh, ppWl, KS * D, 128,
                                  pZ0h, pZ0l, D, 0,
                                  pYt, V, (long)D * V,
                                  1, 128, nullptr, nullptr, 0);
    split(pYt, pYth, pYtl, (long)KS * D * V);

    // 3) diffusion: 12 partials (3 scales x 4 K-splits), M=V, N=128, K=V
    split(kernels, pKh, pKl, (long)KS * V * V);
    k_mm<<<dim3(32, 1, 12), 256>>>(pKh, pKl, V, (long)V * V,
                                   pYth, pYtl, V, (long)D * V,
                                   pPart, D, (long)V * D,
                                   4, 1024, nullptr, nullptr, 0);
    k_reduce12<<<V, 128>>>(pPart, proj_b, pX);

    // 4) transformer layers
    for (int l = 0; l < NL; l++) {
        split(pX, psh, psl, (long)V * D);
        split(Wqkv + (size_t)l * 3 * D * D, pwh, pwl, (long)3 * D * D);
        k_mm<<<dim3(32, 3, 1), 256>>>(psh, psl, D, 0, pwh, pwl, D, 0,
                                      pqkv, 3 * D, 0, 1, 128,
                                      bqkv + l * 3 * D, nullptr, 0);

        k_attn_part<<<dim3(32, NH, 8), 128>>>(pqkv, pop, plp);
        k_comb<<<V, 128>>>(pop, plp, pattn);

        split(pattn, psh, psl, (long)V * D);
        split(Wo + (size_t)l * D * D, pwh, pwl, (long)D * D);
        k_mm<<<dim3(32, 1, 1), 256>>>(psh, psl, D, 0, pwh, pwl, D, 0,
                                      ptmp, D, 0, 1, 128,
                                      bo + l * D, pX, 0);
        k_ln<<<V, 128>>>(ptmp, ln1_g + l * D, ln1_b + l * D, pX);

        split(pX, psh, psl, (long)V * D);
        split(W1 + (size_t)l * FF * D, pwh, pwl, (long)FF * D);
        k_mm<<<dim3(32, 1, 1), 256>>>(psh, psl, D, 0, pwh, pwl, D, 0,
                                      pff, FF, 0, 1, 128,
                                      b1 + l * FF, nullptr, 1);

        split(pff, psh, psl, (long)V * FF);
        split(W2 + (size_t)l * D * FF, pwh, pwl, (long)D * FF);
        k_mm<<<dim3(32, 1, 1), 256>>>(psh, psl, FF, 0, pwh, pwl, FF, 0,
                                      ptmp, D, 0, 1, 128,
                                      b2 + l * D, pX, 0);
        k_ln<<<V, 128>>>(ptmp, ln2_g + l * D, ln2_b + l * D, pX);
    }

    // 5) pooling
    k_pool<<<NVIS, 128>>>(visits, pX, out);
}

// round 6
// speedup vs baseline: 4.3055x; 1.8165x over previous
#include <cuda_runtime.h>
#include <cuda_bf16.h>
#include <cstdint>
#include <cstddef>

#define V    4096
#define D    128
#define KS   3
#define NH   4
#define HD   32
#define FF   128
#define NL   2
#define NVIS 8192
#define MAXC 32

// ===================== scratch ==============================================
__device__ float g_Z0[V * D];
__device__ float g_Yt[KS * D * V];
__device__ float g_part[12 * V * D];
__device__ float g_X[V * D], g_qkv[V * 3 * D], g_attn[V * D], g_tmp[V * D], g_ff[V * FF];
__device__ __nv_bfloat16 g_Qh[NH * V * HD], g_Ql[NH * V * HD];
__device__ __nv_bfloat16 g_KBh[NH * V * HD], g_KBl[NH * V * HD];
__device__ __nv_bfloat16 g_Vh[NH * HD * V], g_Vl[NH * HD * V];

// ===================== helpers ==============================================
__device__ __forceinline__ uint32_t smem_u32(const void* p) {
    uint32_t a;
    asm("{ .reg .u64 t; cvta.to.shared.u64 t, %1; cvt.u32.u64 %0, t; }" : "=r"(a) : "l"(p));
    return a;
}
__device__ __forceinline__ void mma_bf16(float* c, const uint32_t* a, const uint32_t* b) {
    asm volatile("mma.sync.aligned.m16n8k16.row.col.f32.bf16.bf16.f32 "
        "{%0,%1,%2,%3},{%4,%5,%6,%7},{%8,%9},{%0,%1,%2,%3};"
        : "+f"(c[0]), "+f"(c[1]), "+f"(c[2]), "+f"(c[3])
        : "r"(a[0]), "r"(a[1]), "r"(a[2]), "r"(a[3]), "r"(b[0]), "r"(b[1]));
}
__device__ __forceinline__ void ldsm4(uint32_t* r, uint32_t addr) {
    asm volatile("ldmatrix.sync.aligned.m8n8.x4.shared.b16 {%0,%1,%2,%3}, [%4];"
        : "=r"(r[0]), "=r"(r[1]), "=r"(r[2]), "=r"(r[3]) : "r"(addr));
}
__device__ __forceinline__ void split2(float x, float y, uint32_t& hi, uint32_t& lo) {
    __nv_bfloat16 hx = __float2bfloat16(x), hy = __float2bfloat16(y);
    hi = (uint32_t)__bfloat16_as_ushort(hx) | ((uint32_t)__bfloat16_as_ushort(hy) << 16);
    __nv_bfloat16 lx = __float2bfloat16(x - __bfloat162float(hx));
    __nv_bfloat16 ly = __float2bfloat16(y - __bfloat162float(hy));
    lo = (uint32_t)__bfloat16_as_ushort(lx) | ((uint32_t)__bfloat16_as_ushort(ly) << 16);
}
__device__ __forceinline__ uint32_t pack_bf(float x, float y) {
    return (uint32_t)__bfloat16_as_ushort(__float2bfloat16(x)) |
           ((uint32_t)__bfloat16_as_ushort(__float2bfloat16(y)) << 16);
}
__device__ __forceinline__ uint32_t pack_lo(float x, float y) {
    float rx = x - __bfloat162float(__float2bfloat16(x));
    float ry = y - __bfloat162float(__float2bfloat16(y));
    return pack_bf(rx, ry);
}
__device__ __forceinline__ float gelu_f(float x) {
    float t = tanhf(0.7978845608028654f * (x + 0.044715f * x * x * x));
    return 0.5f * x * (1.0f + t);
}

// ===================== elementwise kernels ==================================
__global__ void k_logmap0(const float* __restrict__ X, float* __restrict__ Z) {
    __shared__ float red[128];
    int row = blockIdx.x, d = threadIdx.x;
    float x = X[row * D + d];
    red[d] = x * x;
    __syncthreads();
    for (int s = 64; s > 0; s >>= 1) { if (d < s) red[d] += red[d + s]; __syncthreads(); }
    float norm = sqrtf(red[0]);
    float nc = fminf(fmaxf(norm, 1e-7f), 1.0f - 1e-5f);
    float at = 0.5f * logf((1.0f + nc) / (1.0f - nc));
    Z[row * D + d] = (at / fmaxf(norm, 1e-7f)) * x;
}

__global__ void k_reduce12(const float* __restrict__ part, const float* __restrict__ bias,
                           float* __restrict__ X) {
    int m = blockIdx.x, d = threadIdx.x;
    float s = bias[d];
    #pragma unroll
    for (int i = 0; i < 12; i++) s += part[((size_t)i * V + m) * D + d];
    X[m * D + d] = s;
}

__global__ void k_ln(const float* __restrict__ in, const float* __restrict__ g,
                     const float* __restrict__ b, float* __restrict__ out) {
    __shared__ float red[128];
    int row = blockIdx.x, d = threadIdx.x;
    float x = in[row * D + d];
    red[d] = x;
    __syncthreads();
    for (int s = 64; s > 0; s >>= 1) { if (d < s) red[d] += red[d + s]; __syncthreads(); }
    float mean = red[0] * (1.0f / 128.0f);
    __syncthreads();
    float c = x - mean;
    red[d] = c * c;
    __syncthreads();
    for (int s = 64; s > 0; s >>= 1) { if (d < s) red[d] += red[d + s]; __syncthreads(); }
    float var = red[0] * (1.0f / 128.0f);
    out[row * D + d] = c * rsqrtf(var + 1e-5f) * g[d] + b[d];
}

__global__ void k_pool(const int* __restrict__ visits, const float* __restrict__ Xf,
                       float* __restrict__ out) {
    int vis = blockIdx.x, d = threadIdx.x;
    float s = 0.0f;
    int cnt = 0;
    #pragma unroll 8
    for (int c = 0; c < MAXC; c++) {
        int code = visits[vis * MAXC + c];
        if (code != 0) { cnt++; s += Xf[(size_t)code * D + d]; }
    }
    out[(size_t)vis * D + d] = (cnt > 0) ? (s / (float)cnt) : 0.0f;
}

__global__ void k_prep_qk(const float* __restrict__ qkv,
                          __nv_bfloat16* __restrict__ Qh, __nv_bfloat16* __restrict__ Ql,
                          __nv_bfloat16* __restrict__ Kh, __nv_bfloat16* __restrict__ Kl) {
    int idx = blockIdx.x * 256 + threadIdx.x;
    int d = idx & 31, q = (idx >> 5) & (V - 1), h = idx >> 17;
    float qv = qkv[(size_t)q * 384 + h * 32 + d] * 0.17677669529663687f;
    float kv = qkv[(size_t)q * 384 + 128 + h * 32 + d];
    size_t o = ((size_t)h * V + q) * HD + d;
    __nv_bfloat16 a = __float2bfloat16(qv);
    Qh[o] = a; Ql[o] = __float2bfloat16(qv - __bfloat162float(a));
    a = __float2bfloat16(kv);
    Kh[o] = a; Kl[o] = __float2bfloat16(kv - __bfloat162float(a));
}

__global__ void k_prep_v(const float* __restrict__ qkv,
                         __nv_bfloat16* __restrict__ Vh, __nv_bfloat16* __restrict__ Vl) {
    int idx = blockIdx.x * 256 + threadIdx.x;
    int t = idx & (V - 1), d = (idx >> 12) & 31, h = idx >> 17;
    float v = qkv[(size_t)t * 384 + 256 + h * 32 + d];
    size_t o = ((size_t)h * HD + d) * V + t;
    __nv_bfloat16 a = __float2bfloat16(v);
    Vh[o] = a; Vl[o] = __float2bfloat16(v - __bfloat162float(a));
}

// ===================== generic HMMA GEMM (fp32 in, inline split) ============
__global__ __launch_bounds__(256) void k_mm(
    const float* __restrict__ A, int lda, long sA,
    const float* __restrict__ W, int ldw, long sW,
    float* __restrict__ C, int ldc, long sC,
    int ksplit, int ksub,
    const float* __restrict__ bias, const float* __restrict__ resid, int gelu)
{
    __shared__ __align__(16) char sm[4][128 * 80];
    int tid = threadIdx.x, lane = tid & 31, wid = tid >> 5;
    int z = blockIdx.z, s = z / ksplit, j = z - s * ksplit;
    A += (long)s * sA; W += (long)s * sW; C += (long)z * sC;
    int m0 = blockIdx.x * 128, n0 = blockIdx.y * 128, k0 = j * ksub;
    int wm = wid & 3, wn = wid >> 2, mb = wm * 32, nb = wn * 64;
    int g = lane >> 2, tg = lane & 3;
    int l8 = lane & 7, q4 = lane >> 3;
    int a_ro = ((q4 & 1) << 3) + l8, a_co = (q4 >> 1) << 3;
    int b_ro = ((q4 >> 1) << 3) + l8, b_co = (q4 & 1) << 3;
    uint32_t smb = smem_u32(sm);

    float acc[2][8][4];
    #pragma unroll
    for (int a = 0; a < 2; a++)
        #pragma unroll
        for (int b = 0; b < 8; b++)
            #pragma unroll
            for (int c = 0; c < 4; c++) acc[a][b][c] = 0.0f;

    int r = tid >> 1, qq = tid & 1;
    const float4* pa = (const float4*)(A + (size_t)(m0 + r) * lda + k0 + qq * 16);
    const float4* pw = (const float4*)(W + (size_t)(n0 + r) * ldw + k0 + qq * 16);
    float4 ra[4], rw[4];
    #pragma unroll
    for (int i = 0; i < 4; i++) { ra[i] = pa[i]; rw[i] = pw[i]; }
    int astep = 8, wstep = 8;  // 32 floats / 4 per float4

    for (int c0 = k0; c0 < k0 + ksub; c0 += 32) {
        __syncthreads();
        #pragma unroll
        for (int i = 0; i < 4; i++) {
            uint32_t h0, l0, h1, l1;
            int off = r * 80 + (qq * 16 + i * 4) * 2;
            split2(ra[i].x, ra[i].y, h0, l0);
            split2(ra[i].z, ra[i].w, h1, l1);
            *(uint32_t*)(sm[0] + off) = h0; *(uint32_t*)(sm[0] + off + 4) = h1;
            *(uint32_t*)(sm[1] + off) = l0; *(uint32_t*)(sm[1] + off + 4) = l1;
            split2(rw[i].x, rw[i].y, h0, l0);
            split2(rw[i].z, rw[i].w, h1, l1);
            *(uint32_t*)(sm[2] + off) = h0; *(uint32_t*)(sm[2] + off + 4) = h1;
            *(uint32_t*)(sm[3] + off) = l0; *(uint32_t*)(sm[3] + off + 4) = l1;
        }
        __syncthreads();
        if (c0 + 32 < k0 + ksub) {
            pa += astep; pw += wstep;
            #pragma unroll
            for (int i = 0; i < 4; i++) { ra[i] = pa[i]; rw[i] = pw[i]; }
        }
        #pragma unroll
        for (int kk = 0; kk < 32; kk += 16) {
            uint32_t ah[2][4], al[2][4], bh[8][2], bl[8][2], t[4];
            #pragma unroll
            for (int mf = 0; mf < 2; mf++) {
                uint32_t ad = smb + (mb + mf * 16 + a_ro) * 80 + (kk + a_co) * 2;
                ldsm4(ah[mf], ad);
                ldsm4(al[mf], ad + 10240);
            }
            #pragma unroll
            for (int nf2 = 0; nf2 < 4; nf2++) {
                uint32_t bd = smb + 20480 + (nb + nf2 * 16 + b_ro) * 80 + (kk + b_co) * 2;
                ldsm4(t, bd);
                bh[2*nf2][0] = t[0]; bh[2*nf2][1] = t[1];
                bh[2*nf2+1][0] = t[2]; bh[2*nf2+1][1] = t[3];
                ldsm4(t, bd + 10240);
                bl[2*nf2][0] = t[0]; bl[2*nf2][1] = t[1];
                bl[2*nf2+1][0] = t[2]; bl[2*nf2+1][1] = t[3];
            }
            #pragma unroll
            for (int mf = 0; mf < 2; mf++)
                #pragma unroll
                for (int nf = 0; nf < 8; nf++) {
                    mma_bf16(acc[mf][nf], ah[mf], bh[nf]);
                    mma_bf16(acc[mf][nf], al[mf], bh[nf]);
                    mma_bf16(acc[mf][nf], ah[mf], bl[nf]);
                }
        }
    }

    #pragma unroll
    for (int mf = 0; mf < 2; mf++)
        #pragma unroll
        for (int nf = 0; nf < 8; nf++) {
            int m = m0 + mb + mf * 16 + g;
            int n = n0 + nb + nf * 8 + tg * 2;
            float v0 = acc[mf][nf][0], v1 = acc[mf][nf][1];
            float v2 = acc[mf][nf][2], v3 = acc[mf][nf][3];
            if (bias) {
                float b0 = bias[n], b1 = bias[n + 1];
                v0 += b0; v1 += b1; v2 += b0; v3 += b1;
            }
            if (resid) {
                float2 r0 = *(const float2*)&resid[(size_t)m * ldc + n];
                float2 r1 = *(const float2*)&resid[(size_t)(m + 8) * ldc + n];
                v0 += r0.x; v1 += r0.y; v2 += r1.x; v3 += r1.y;
            }
            if (gelu) { v0 = gelu_f(v0); v1 = gelu_f(v1); v2 = gelu_f(v2); v3 = gelu_f(v3); }
            *(float2*)&C[(size_t)m * ldc + n] = make_float2(v0, v1);
            *(float2*)&C[(size_t)(m + 8) * ldc + n] = make_float2(v2, v3);
        }
}

// ===================== fused HMMA flash attention ===========================
// smem: K hi [128][80] @0, K lo @10240, Vt hi [32][272] @20480, Vt lo @29184,
//       rowsum [2][128] f32 @37888. O-combine [128][34] f32 aliases @0.
__global__ __launch_bounds__(256) void k_flash(
    const __nv_bfloat16* __restrict__ Qh, const __nv_bfloat16* __restrict__ Ql,
    const __nv_bfloat16* __restrict__ Kh, const __nv_bfloat16* __restrict__ Kl,
    const __nv_bfloat16* __restrict__ Vth, const __nv_bfloat16* __restrict__ Vtl,
    float* __restrict__ attn)
{
    __shared__ __align__(16) char sm[38912];
    uint32_t smb = smem_u32(sm);
    int tid = threadIdx.x, lane = tid & 31, wid = tid >> 5;
    int wm = wid & 3, wn = wid >> 2;
    int g = lane >> 2, tg = lane & 3;
    int l8 = lane & 7, q4 = lane >> 3;
    int a_ro = ((q4 & 1) << 3) + l8, a_co = (q4 >> 1) << 3;
    int b_ro = ((q4 >> 1) << 3) + l8, b_co = (q4 & 1) << 3;
    int h = blockIdx.y, q0 = blockIdx.x * 128;

    // stage Q in K area, grab fragments
    {
        int r = tid >> 1, qq = tid & 1;
        const uint4* s1 = (const uint4*)(Qh + ((size_t)h * V + q0 + r) * HD + qq * 16);
        const uint4* s2 = (const uint4*)(Ql + ((size_t)h * V + q0 + r) * HD + qq * 16);
        *(uint4*)(sm + r * 80 + qq * 32) = s1[0];
        *(uint4*)(sm + r * 80 + qq * 32 + 16) = s1[1];
        *(uint4*)(sm + 10240 + r * 80 + qq * 32) = s2[0];
        *(uint4*)(sm + 10240 + r * 80 + qq * 32 + 16) = s2[1];
    }
    __syncthreads();
    uint32_t qfh[2][2][4], qfl[2][2][4];
    #pragma unroll
    for (int mf = 0; mf < 2; mf++)
        #pragma unroll
        for (int kk = 0; kk < 2; kk++) {
            uint32_t ad = smb + (wm * 32 + mf * 16 + a_ro) * 80 + (kk * 16 + a_co) * 2;
            ldsm4(qfh[mf][kk], ad);
            ldsm4(qfl[mf][kk], ad + 10240);
        }
    __syncthreads();

    float oacc[2][4][4];
    #pragma unroll
    for (int a = 0; a < 2; a++)
        #pragma unroll
        for (int b = 0; b < 4; b++)
            #pragma unroll
            for (int c = 0; c < 4; c++) oacc[a][b][c] = 0.0f;
    float rs[2][2] = {{0.0f, 0.0f}, {0.0f, 0.0f}};

    for (int kt = 0; kt < 32; kt++) {
        {   // K tile [128 keys][32 d] + Vt tile [32 d][128 keys]
            int r = tid >> 1, qq = tid & 1;
            const uint4* s1 = (const uint4*)(Kh + ((size_t)h * V + kt * 128 + r) * HD + qq * 16);
            const uint4* s2 = (const uint4*)(Kl + ((size_t)h * V + kt * 128 + r) * HD + qq * 16);
            *(uint4*)(sm + r * 80 + qq * 32) = s1[0];
            *(uint4*)(sm + r * 80 + qq * 32 + 16) = s1[1];
            *(uint4*)(sm + 10240 + r * 80 + qq * 32) = s2[0];
            *(uint4*)(sm + 10240 + r * 80 + qq * 32 + 16) = s2[1];
            int r2 = tid >> 3, q2 = tid & 7;
            const uint4* s3 = (const uint4*)(Vth + ((size_t)h * HD + r2) * V + kt * 128 + q2 * 16);
            const uint4* s4 = (const uint4*)(Vtl + ((size_t)h * HD + r2) * V + kt * 128 + q2 * 16);
            *(uint4*)(sm + 20480 + r2 * 272 + q2 * 32) = s3[0];
            *(uint4*)(sm + 20480 + r2 * 272 + q2 * 32 + 16) = s3[1];
            *(uint4*)(sm + 29184 + r2 * 272 + q2 * 32) = s4[0];
            *(uint4*)(sm + 29184 + r2 * 272 + q2 * 32 + 16) = s4[1];
        }
        __syncthreads();

        // S = Q K^T over this warp's 64 key-columns
        float sacc[2][8][4];
        #pragma unroll
        for (int a = 0; a < 2; a++)
            #pragma unroll
            for (int b = 0; b < 8; b++)
                #pragma unroll
                for (int c = 0; c < 4; c++) sacc[a][b][c] = 0.0f;
        #pragma unroll
        for (int kk = 0; kk < 2; kk++) {
            uint32_t bh[8][2], bl[8][2], t[4];
            #pragma unroll
            for (int nf2 = 0; nf2 < 4; nf2++) {
                uint32_t bd = smb + (wn * 64 + nf2 * 16 + b_ro) * 80 + (kk * 16 + b_co) * 2;
                ldsm4(t, bd);
                bh[2*nf2][0] = t[0]; bh[2*nf2][1] = t[1];
                bh[2*nf2+1][0] = t[2]; bh[2*nf2+1][1] = t[3];
                ldsm4(t, bd + 10240);
                bl[2*nf2][0] = t[0]; bl[2*nf2][1] = t[1];
                bl[2*nf2+1][0] = t[2]; bl[2*nf2+1][1] = t[3];
            }
            #pragma unroll
            for (int mf = 0; mf < 2; mf++)
                #pragma unroll
                for (int nf = 0; nf < 8; nf++) {
                    mma_bf16(sacc[mf][nf], qfh[mf][kk], bh[nf]);
                    mma_bf16(sacc[mf][nf], qfl[mf][kk], bh[nf]);
                    mma_bf16(sacc[mf][nf], qfh[mf][kk], bl[nf]);
                }
        }
        // exp in place + rowsum
        #pragma unroll
        for (int mf = 0; mf < 2; mf++)
            #pragma unroll
            for (int nf = 0; nf < 8; nf++) {
                float* c = sacc[mf][nf];
                c[0] = __expf(c[0]); c[1] = __expf(c[1]);
                c[2] = __expf(c[2]); c[3] = __expf(c[3]);
                rs[mf][0] += c[0] + c[1];
                rs[mf][1] += c[2] + c[3];
            }
        // O += P V  (A-frags built from sacc in registers)
        #pragma unroll
        for (int j2 = 0; j2 < 4; j2++) {
            uint32_t vbh[4][2], vbl[4][2], t[4];
            #pragma unroll
            for (int nf2 = 0; nf2 < 2; nf2++) {
                uint32_t bd = smb + 20480 + (nf2 * 16 + b_ro) * 272 + (wn * 64 + j2 * 16 + b_co) * 2;
                ldsm4(t, bd);
                vbh[2*nf2][0] = t[0]; vbh[2*nf2][1] = t[1];
                vbh[2*nf2+1][0] = t[2]; vbh[2*nf2+1][1] = t[3];
                ldsm4(t, bd + 8704);
                vbl[2*nf2][0] = t[0]; vbl[2*nf2][1] = t[1];
                vbl[2*nf2+1][0] = t[2]; vbl[2*nf2+1][1] = t[3];
            }
            #pragma unroll
            for (int mf = 0; mf < 2; mf++) {
                const float* p0 = sacc[mf][2 * j2];
                const float* p1 = sacc[mf][2 * j2 + 1];
                uint32_t ah[4], al[4];
                ah[0] = pack_bf(p0[0], p0[1]); al[0] = pack_lo(p0[0], p0[1]);
                ah[1] = pack_bf(p0[2], p0[3]); al[1] = pack_lo(p0[2], p0[3]);
                ah[2] = pack_bf(p1[0], p1[1]); al[2] = pack_lo(p1[0], p1[1]);
                ah[3] = pack_bf(p1[2], p1[3]); al[3] = pack_lo(p1[2], p1[3]);
                #pragma unroll
                for (int nf = 0; nf < 4; nf++) {
                    mma_bf16(oacc[mf][nf], ah, vbh[nf]);
                    mma_bf16(oacc[mf][nf], al, vbh[nf]);
                    mma_bf16(oacc[mf][nf], ah, vbl[nf]);
                }
            }
        }
        __syncthreads();
    }

    // rowsum: reduce over quad (tg), publish per key-half
    float* rsb = (float*)(sm + 37888);
    #pragma unroll
    for (int mf = 0; mf < 2; mf++)
        #pragma unroll
        for (int i = 0; i < 2; i++) {
            float v = rs[mf][i];
            v += __shfl_xor_sync(0xFFFFFFFF, v, 1);
            v += __shfl_xor_sync(0xFFFFFFFF, v, 2);
            rs[mf][i] = v;
        }
    if (tg == 0) {
        #pragma unroll
        for (int mf = 0; mf < 2; mf++) {
            rsb[wn * 128 + wm * 32 + mf * 16 + g] = rs[mf][0];
            rsb[wn * 128 + wm * 32 + mf * 16 + g + 8] = rs[mf][1];
        }
    }
    // O combine across key halves via smem [128][34]
    float* Osm = (float*)sm;
    __syncthreads();
    if (wn == 1) {
        #pragma unroll
        for (int mf = 0; mf < 2; mf++)
            #pragma unroll
            for (int nf = 0; nf < 4; nf++) {
                int row = wm * 32 + mf * 16 + g, col = nf * 8 + tg * 2;
                Osm[row * 34 + col] = oacc[mf][nf][0];
                Osm[row * 34 + col + 1] = oacc[mf][nf][1];
                Osm[(row + 8) * 34 + col] = oacc[mf][nf][2];
                Osm[(row + 8) * 34 + col + 1] = oacc[mf][nf][3];
            }
    }
    __syncthreads();
    if (wn == 0) {
        #pragma unroll
        for (int mf = 0; mf < 2; mf++) {
            int row = wm * 32 + mf * 16 + g;
            float inv0 = 1.0f / (rsb[row] + rsb[128 + row]);
            float inv1 = 1.0f / (rsb[row + 8] + rsb[128 + row + 8]);
            #pragma unroll
            for (int nf = 0; nf < 4; nf++) {
                int col = nf * 8 + tg * 2;
                float2 v0 = make_float2((oacc[mf][nf][0] + Osm[row * 34 + col]) * inv0,
                                        (oacc[mf][nf][1] + Osm[row * 34 + col + 1]) * inv0);
                float2 v1 = make_float2((oacc[mf][nf][2] + Osm[(row + 8) * 34 + col]) * inv1,
                                        (oacc[mf][nf][3] + Osm[(row + 8) * 34 + col + 1]) * inv1);
                *(float2*)&attn[(size_t)(q0 + row) * D + h * 32 + col] = v0;
                *(float2*)&attn[(size_t)(q0 + row + 8) * D + h * 32 + col] = v1;
            }
        }
    }
}

// ===================== host orchestration ===================================
extern "C" void kernel_launch(void* const* d_in, const int* in_sizes, int n_in,
                              void* d_out, int out_size)
{
    const int*   visits  = (const int*)d_in[0];
    const float* X_hyp   = (const float*)d_in[1];
    const float* kernels = (const float*)d_in[2];
    const float* proj_W  = (const float*)d_in[3];
    const float* proj_b  = (const float*)d_in[4];
    const float* Wqkv    = (const float*)d_in[5];
    const float* bqkv    = (const float*)d_in[6];
    const float* Wo      = (const float*)d_in[7];
    const float* bo      = (const float*)d_in[8];
    const float* W1      = (const float*)d_in[9];
    const float* b1      = (const float*)d_in[10];
    const float* W2      = (const float*)d_in[11];
    const float* b2      = (const float*)d_in[12];
    const float* ln1_g   = (const float*)d_in[13];
    const float* ln1_b   = (const float*)d_in[14];
    const float* ln2_g   = (const float*)d_in[15];
    const float* ln2_b   = (const float*)d_in[16];
    float* out = (float*)d_out;

    float *pZ0, *pYt, *pPart, *pX, *pqkv, *pattn, *ptmp, *pff;
    __nv_bfloat16 *pQh, *pQl, *pKh, *pKl, *pVh, *pVl;
    cudaGetSymbolAddress((void**)&pZ0, g_Z0);
    cudaGetSymbolAddress((void**)&pYt, g_Yt);
    cudaGetSymbolAddress((void**)&pPart, g_part);
    cudaGetSymbolAddress((void**)&pX, g_X);
    cudaGetSymbolAddress((void**)&pqkv, g_qkv);
    cudaGetSymbolAddress((void**)&pattn, g_attn);
    cudaGetSymbolAddress((void**)&ptmp, g_tmp);
    cudaGetSymbolAddress((void**)&pff, g_ff);
    cudaGetSymbolAddress((void**)&pQh, g_Qh);
    cudaGetSymbolAddress((void**)&pQl, g_Ql);
    cudaGetSymbolAddress((void**)&pKh, g_KBh);
    cudaGetSymbolAddress((void**)&pKl, g_KBl);
    cudaGetSymbolAddress((void**)&pVh, g_Vh);
    cudaGetSymbolAddress((void**)&pVl, g_Vl);

    // 1) logmap0
    k_logmap0<<<V, 128>>>(X_hyp, pZ0);

    // 2) Yt[s][n][v] = sum_d proj_W[n, s*128+d] * Z0[v, d]
    k_mm<<<dim3(1, 32, 3), 256>>>(proj_W, KS * D, 128,
                                  pZ0, D, 0,
                                  pYt, V, (long)D * V,
                                  1, 128, nullptr, nullptr, 0);

    // 3) diffusion: part[z] = kernels[s][mtile] @ Yt[s]^T over k-range j
    k_mm<<<dim3(32, 1, 12), 256>>>(kernels, V, (long)V * V,
                                   pYt, V, (long)D * V,
                                   pPart, D, (long)V * D,
                                   4, 1024, nullptr, nullptr, 0);
    k_reduce12<<<V, 128>>>(pPart, proj_b, pX);

    // 4) transformer layers
    for (int l = 0; l < NL; l++) {
        k_mm<<<dim3(32, 3, 1), 256>>>(pX, D, 0,
                                      Wqkv + (size_t)l * 3 * D * D, D, 0,
                                      pqkv, 3 * D, 0, 1, 128,
                                      bqkv + l * 3 * D, nullptr, 0);

        k_prep_qk<<<2048, 256>>>(pqkv, pQh, pQl, pKh, pKl);
        k_prep_v<<<2048, 256>>>(pqkv, pVh, pVl);
        k_flash<<<dim3(32, NH), 256>>>(pQh, pQl, pKh, pKl, pVh, pVl, pattn);

        k_mm<<<dim3(32, 1, 1), 256>>>(pattn, D, 0,
                                      Wo + (size_t)l * D * D, D, 0,
                                      ptmp, D, 0, 1, 128,
                                      bo + l * D, pX, 0);
        k_ln<<<V, 128>>>(ptmp, ln1_g + l * D, ln1_b + l * D, pX);

        k_mm<<<dim3(32, 1, 1), 256>>>(pX, D, 0,
                                      W1 + (size_t)l * FF * D, D, 0,
                                      pff, FF, 0, 1, 128,
                                      b1 + l * FF, nullptr, 1);
        k_mm<<<dim3(32, 1, 1), 256>>>(pff, FF, 0,
                                      W2 + (size_t)l * D * FF, FF, 0,
                                      ptmp, D, 0, 1, 128,
                                      b2 + l * D, pX, 0);
        k_ln<<<V, 128>>>(ptmp, ln2_g + l * D, ln2_b + l * D, pX);
    }

    // 5) pooling
    k_pool<<<NVIS, 128>>>(visits, pX, out);
}

// round 7
// speedup vs baseline: 4.3746x; 1.0160x over previous
#include <cuda_runtime.h>
#include <cuda_bf16.h>
#include <cstdint>
#include <cstddef>

#define V    4096
#define D    128
#define KS   3
#define NH   4
#define HD   32
#define FF   128
#define NL   2
#define NVIS 8192
#define MAXC 32

// ===================== scratch ==============================================
__device__ float g_Z0[V * D];
__device__ float g_Yt[KS * D * V];
__device__ float g_part[12 * V * D];
__device__ float g_X[V * D], g_qkv[V * 3 * D], g_attn[V * D], g_ff[V * FF];
__device__ __nv_bfloat16 g_Qh[NH * V * HD], g_Ql[NH * V * HD];
__device__ __nv_bfloat16 g_KBh[NH * V * HD], g_KBl[NH * V * HD];
__device__ __nv_bfloat16 g_Vh[NH * HD * V], g_Vl[NH * HD * V];
__device__ float g_opart[NH * 8 * V * HD];
__device__ float g_lpart[NH * 8 * V];

// ===================== helpers ==============================================
__device__ __forceinline__ uint32_t smem_u32(const void* p) {
    uint32_t a;
    asm("{ .reg .u64 t; cvta.to.shared.u64 t, %1; cvt.u32.u64 %0, t; }" : "=r"(a) : "l"(p));
    return a;
}
__device__ __forceinline__ void mma_bf16(float* c, const uint32_t* a, const uint32_t* b) {
    asm volatile("mma.sync.aligned.m16n8k16.row.col.f32.bf16.bf16.f32 "
        "{%0,%1,%2,%3},{%4,%5,%6,%7},{%8,%9},{%0,%1,%2,%3};"
        : "+f"(c[0]), "+f"(c[1]), "+f"(c[2]), "+f"(c[3])
        : "r"(a[0]), "r"(a[1]), "r"(a[2]), "r"(a[3]), "r"(b[0]), "r"(b[1]));
}
__device__ __forceinline__ void ldsm4(uint32_t* r, uint32_t addr) {
    asm volatile("ldmatrix.sync.aligned.m8n8.x4.shared.b16 {%0,%1,%2,%3}, [%4];"
        : "=r"(r[0]), "=r"(r[1]), "=r"(r[2]), "=r"(r[3]) : "r"(addr));
}
__device__ __forceinline__ void split2(float x, float y, uint32_t& hi, uint32_t& lo) {
    __nv_bfloat16 hx = __float2bfloat16(x), hy = __float2bfloat16(y);
    hi = (uint32_t)__bfloat16_as_ushort(hx) | ((uint32_t)__bfloat16_as_ushort(hy) << 16);
    __nv_bfloat16 lx = __float2bfloat16(x - __bfloat162float(hx));
    __nv_bfloat16 ly = __float2bfloat16(y - __bfloat162float(hy));
    lo = (uint32_t)__bfloat16_as_ushort(lx) | ((uint32_t)__bfloat16_as_ushort(ly) << 16);
}
__device__ __forceinline__ uint32_t pack_bf(float x, float y) {
    return (uint32_t)__bfloat16_as_ushort(__float2bfloat16(x)) |
           ((uint32_t)__bfloat16_as_ushort(__float2bfloat16(y)) << 16);
}
__device__ __forceinline__ uint32_t pack_lo(float x, float y) {
    float rx = x - __bfloat162float(__float2bfloat16(x));
    float ry = y - __bfloat162float(__float2bfloat16(y));
    return pack_bf(rx, ry);
}
__device__ __forceinline__ float gelu_f(float x) {
    float t = tanhf(0.7978845608028654f * (x + 0.044715f * x * x * x));
    return 0.5f * x * (1.0f + t);
}

// ===================== elementwise kernels ==================================
__global__ void k_logmap0(const float* __restrict__ X, float* __restrict__ Z) {
    __shared__ float red[128];
    int row = blockIdx.x, d = threadIdx.x;
    float x = X[row * D + d];
    red[d] = x * x;
    __syncthreads();
    for (int s = 64; s > 0; s >>= 1) { if (d < s) red[d] += red[d + s]; __syncthreads(); }
    float norm = sqrtf(red[0]);
    float nc = fminf(fmaxf(norm, 1e-7f), 1.0f - 1e-5f);
    float at = 0.5f * logf((1.0f + nc) / (1.0f - nc));
    Z[row * D + d] = (at / fmaxf(norm, 1e-7f)) * x;
}

__global__ void k_reduce12(const float* __restrict__ part, const float* __restrict__ bias,
                           float* __restrict__ X) {
    int m = blockIdx.x, d = threadIdx.x;
    float s = bias[d];
    #pragma unroll
    for (int i = 0; i < 12; i++) s += part[((size_t)i * V + m) * D + d];
    X[m * D + d] = s;
}

__global__ void k_pool(const int* __restrict__ visits, const float* __restrict__ Xf,
                       float* __restrict__ out) {
    int vis = blockIdx.x, d = threadIdx.x;
    float s = 0.0f;
    int cnt = 0;
    #pragma unroll 8
    for (int c = 0; c < MAXC; c++) {
        int code = visits[vis * MAXC + c];
        if (code != 0) { cnt++; s += Xf[(size_t)code * D + d]; }
    }
    out[(size_t)vis * D + d] = (cnt > 0) ? (s / (float)cnt) : 0.0f;
}

__global__ void k_prep_qk(const float* __restrict__ qkv,
                          __nv_bfloat16* __restrict__ Qh, __nv_bfloat16* __restrict__ Ql,
                          __nv_bfloat16* __restrict__ Kh, __nv_bfloat16* __restrict__ Kl) {
    int idx = blockIdx.x * 256 + threadIdx.x;
    int d = idx & 31, q = (idx >> 5) & (V - 1), h = idx >> 17;
    float qv = qkv[(size_t)q * 384 + h * 32 + d] * 0.17677669529663687f;
    float kv = qkv[(size_t)q * 384 + 128 + h * 32 + d];
    size_t o = ((size_t)h * V + q) * HD + d;
    __nv_bfloat16 a = __float2bfloat16(qv);
    Qh[o] = a; Ql[o] = __float2bfloat16(qv - __bfloat162float(a));
    a = __float2bfloat16(kv);
    Kh[o] = a; Kl[o] = __float2bfloat16(kv - __bfloat162float(a));
}

__global__ void k_prep_v(const float* __restrict__ qkv,
                         __nv_bfloat16* __restrict__ Vh, __nv_bfloat16* __restrict__ Vl) {
    int idx = blockIdx.x * 256 + threadIdx.x;
    int t = idx & (V - 1), d = (idx >> 12) & 31, h = idx >> 17;
    float v = qkv[(size_t)t * 384 + 256 + h * 32 + d];
    size_t o = ((size_t)h * HD + d) * V + t;
    __nv_bfloat16 a = __float2bfloat16(v);
    Vh[o] = a; Vl[o] = __float2bfloat16(v - __bfloat162float(a));
}

__global__ void k_comb2(const float* __restrict__ op, const float* __restrict__ lp,
                        float* __restrict__ attn) {
    int q = blockIdx.x, h = threadIdx.x >> 5, d = threadIdx.x & 31;
    size_t b0 = (size_t)(h * 2) * V + q, b1 = (size_t)(h * 2 + 1) * V + q;
    float o = op[b0 * 32 + d] + op[b1 * 32 + d];
    float l = lp[b0] + lp[b1];
    attn[(size_t)q * D + h * 32 + d] = o / l;
}

// ===================== generic HMMA GEMM (fp32 in, inline split, opt LN) ====
__global__ __launch_bounds__(256) void k_mm(
    const float* __restrict__ A, int lda, long sA,
    const float* __restrict__ W, int ldw, long sW,
    float* __restrict__ C, int ldc, long sC,
    int ksplit, int ksub,
    const float* __restrict__ bias, const float* __restrict__ resid, int gelu,
    const float* __restrict__ lng, const float* __restrict__ lnb)
{
    __shared__ __align__(16) char sm[4][128 * 80];
    int tid = threadIdx.x, lane = tid & 31, wid = tid >> 5;
    int z = blockIdx.z, s = z / ksplit, j = z - s * ksplit;
    A += (long)s * sA; W += (long)s * sW; C += (long)z * sC;
    int m0 = blockIdx.x * 128, n0 = blockIdx.y * 128, k0 = j * ksub;
    int wm = wid & 3, wn = wid >> 2, mb = wm * 32, nb = wn * 64;
    int g = lane >> 2, tg = lane & 3;
    int l8 = lane & 7, q4 = lane >> 3;
    int a_ro = ((q4 & 1) << 3) + l8, a_co = (q4 >> 1) << 3;
    int b_ro = ((q4 >> 1) << 3) + l8, b_co = (q4 & 1) << 3;
    uint32_t smb = smem_u32(sm);

    float acc[2][8][4];
    #pragma unroll
    for (int a = 0; a < 2; a++)
        #pragma unroll
        for (int b = 0; b < 8; b++)
            #pragma unroll
            for (int c = 0; c < 4; c++) acc[a][b][c] = 0.0f;

    int r = tid >> 1, qq = tid & 1;
    const float4* pa = (const float4*)(A + (size_t)(m0 + r) * lda + k0 + qq * 16);
    const float4* pw = (const float4*)(W + (size_t)(n0 + r) * ldw + k0 + qq * 16);
    float4 ra[4], rw[4];
    #pragma unroll
    for (int i = 0; i < 4; i++) { ra[i] = pa[i]; rw[i] = pw[i]; }

    for (int c0 = k0; c0 < k0 + ksub; c0 += 32) {
        __syncthreads();
        #pragma unroll
        for (int i = 0; i < 4; i++) {
            uint32_t h0, l0, h1, l1;
            int off = r * 80 + (qq * 16 + i * 4) * 2;
            split2(ra[i].x, ra[i].y, h0, l0);
            split2(ra[i].z, ra[i].w, h1, l1);
            *(uint32_t*)(sm[0] + off) = h0; *(uint32_t*)(sm[0] + off + 4) = h1;
            *(uint32_t*)(sm[1] + off) = l0; *(uint32_t*)(sm[1] + off + 4) = l1;
            split2(rw[i].x, rw[i].y, h0, l0);
            split2(rw[i].z, rw[i].w, h1, l1);
            *(uint32_t*)(sm[2] + off) = h0; *(uint32_t*)(sm[2] + off + 4) = h1;
            *(uint32_t*)(sm[3] + off) = l0; *(uint32_t*)(sm[3] + off + 4) = l1;
        }
        __syncthreads();
        if (c0 + 32 < k0 + ksub) {
            pa += 8; pw += 8;
            #pragma unroll
            for (int i = 0; i < 4; i++) { ra[i] = pa[i]; rw[i] = pw[i]; }
        }
        #pragma unroll
        for (int kk = 0; kk < 32; kk += 16) {
            uint32_t ah[2][4], al[2][4], bh[8][2], bl[8][2], t[4];
            #pragma unroll
            for (int mf = 0; mf < 2; mf++) {
                uint32_t ad = smb + (mb + mf * 16 + a_ro) * 80 + (kk + a_co) * 2;
                ldsm4(ah[mf], ad);
                ldsm4(al[mf], ad + 10240);
            }
            #pragma unroll
            for (int nf2 = 0; nf2 < 4; nf2++) {
                uint32_t bd = smb + 20480 + (nb + nf2 * 16 + b_ro) * 80 + (kk + b_co) * 2;
                ldsm4(t, bd);
                bh[2*nf2][0] = t[0]; bh[2*nf2][1] = t[1];
                bh[2*nf2+1][0] = t[2]; bh[2*nf2+1][1] = t[3];
                ldsm4(t, bd + 10240);
                bl[2*nf2][0] = t[0]; bl[2*nf2][1] = t[1];
                bl[2*nf2+1][0] = t[2]; bl[2*nf2+1][1] = t[3];
            }
            #pragma unroll
            for (int mf = 0; mf < 2; mf++)
                #pragma unroll
                for (int nf = 0; nf < 8; nf++) {
                    mma_bf16(acc[mf][nf], ah[mf], bh[nf]);
                    mma_bf16(acc[mf][nf], al[mf], bh[nf]);
                    mma_bf16(acc[mf][nf], ah[mf], bl[nf]);
                }
        }
    }

    // pass 1: finalize acc (bias, residual, gelu)
    #pragma unroll
    for (int mf = 0; mf < 2; mf++)
        #pragma unroll
        for (int nf = 0; nf < 8; nf++) {
            int m = m0 + mb + mf * 16 + g;
            int n = n0 + nb + nf * 8 + tg * 2;
            float* c = acc[mf][nf];
            if (bias) {
                float b0 = bias[n], b1 = bias[n + 1];
                c[0] += b0; c[1] += b1; c[2] += b0; c[3] += b1;
            }
            if (resid) {
                float2 r0 = *(const float2*)&resid[(size_t)m * ldc + n];
                float2 r1 = *(const float2*)&resid[(size_t)(m + 8) * ldc + n];
                c[0] += r0.x; c[1] += r0.y; c[2] += r1.x; c[3] += r1.y;
            }
            if (gelu) {
                c[0] = gelu_f(c[0]); c[1] = gelu_f(c[1]);
                c[2] = gelu_f(c[2]); c[3] = gelu_f(c[3]);
            }
        }

    float mean[2][2], rstd[2][2];
    if (lng) {  // fused LayerNorm: requires gridDim.y==1, N==128
        float sv[2][2] = {{0,0},{0,0}}, qv[2][2] = {{0,0},{0,0}};
        #pragma unroll
        for (int mf = 0; mf < 2; mf++)
            #pragma unroll
            for (int nf = 0; nf < 8; nf++) {
                float* c = acc[mf][nf];
                sv[mf][0] += c[0] + c[1]; qv[mf][0] += c[0]*c[0] + c[1]*c[1];
                sv[mf][1] += c[2] + c[3]; qv[mf][1] += c[2]*c[2] + c[3]*c[3];
            }
        #pragma unroll
        for (int mf = 0; mf < 2; mf++)
            #pragma unroll
            for (int i = 0; i < 2; i++) {
                sv[mf][i] += __shfl_xor_sync(0xFFFFFFFF, sv[mf][i], 1);
                sv[mf][i] += __shfl_xor_sync(0xFFFFFFFF, sv[mf][i], 2);
                qv[mf][i] += __shfl_xor_sync(0xFFFFFFFF, qv[mf][i], 1);
                qv[mf][i] += __shfl_xor_sync(0xFFFFFFFF, qv[mf][i], 2);
            }
        float* S = (float*)sm;
        __syncthreads();
        if (tg == 0) {
            #pragma unroll
            for (int mf = 0; mf < 2; mf++) {
                int rr = mb + mf * 16 + g;
                S[wn * 128 + rr] = sv[mf][0];       S[256 + wn * 128 + rr] = qv[mf][0];
                S[wn * 128 + rr + 8] = sv[mf][1];   S[256 + wn * 128 + rr + 8] = qv[mf][1];
            }
        }
        __syncthreads();
        #pragma unroll
        for (int mf = 0; mf < 2; mf++)
            #pragma unroll
            for (int i = 0; i < 2; i++) {
                int rr = mb + mf * 16 + g + i * 8;
                float mu = (S[rr] + S[128 + rr]) * 0.0078125f;
                float va = (S[256 + rr] + S[384 + rr]) * 0.0078125f - mu * mu;
                mean[mf][i] = mu;
                rstd[mf][i] = rsqrtf(va + 1e-5f);
            }
    }

    #pragma unroll
    for (int mf = 0; mf < 2; mf++)
        #pragma unroll
        for (int nf = 0; nf < 8; nf++) {
            int m = m0 + mb + mf * 16 + g;
            int n = n0 + nb + nf * 8 + tg * 2;
            float* c = acc[mf][nf];
            if (lng) {
                float g0 = lng[n], g1 = lng[n + 1], b0 = lnb[n], b1 = lnb[n + 1];
                c[0] = (c[0] - mean[mf][0]) * rstd[mf][0] * g0 + b0;
                c[1] = (c[1] - mean[mf][0]) * rstd[mf][0] * g1 + b1;
                c[2] = (c[2] - mean[mf][1]) * rstd[mf][1] * g0 + b0;
                c[3] = (c[3] - mean[mf][1]) * rstd[mf][1] * g1 + b1;
            }
            *(float2*)&C[(size_t)m * ldc + n] = make_float2(c[0], c[1]);
            *(float2*)&C[(size_t)(m + 8) * ldc + n] = make_float2(c[2], c[3]);
        }
}

// ===================== fused HMMA flash attention (key-split) ===============
__global__ __launch_bounds__(256) void k_flash(
    const __nv_bfloat16* __restrict__ Qh, const __nv_bfloat16* __restrict__ Ql,
    const __nv_bfloat16* __restrict__ Kh, const __nv_bfloat16* __restrict__ Kl,
    const __nv_bfloat16* __restrict__ Vth, const __nv_bfloat16* __restrict__ Vtl,
    float* __restrict__ opart, float* __restrict__ lpart)
{
    __shared__ __align__(16) char sm[38912];
    uint32_t smb = smem_u32(sm);
    int tid = threadIdx.x, lane = tid & 31, wid = tid >> 5;
    int wm = wid & 3, wn = wid >> 2;
    int g = lane >> 2, tg = lane & 3;
    int l8 = lane & 7, q4 = lane >> 3;
    int a_ro = ((q4 & 1) << 3) + l8, a_co = (q4 >> 1) << 3;
    int b_ro = ((q4 >> 1) << 3) + l8, b_co = (q4 & 1) << 3;
    int h = blockIdx.y, q0 = blockIdx.x * 128, zb = blockIdx.z;

    {
        int r = tid >> 1, qq = tid & 1;
        const uint4* s1 = (const uint4*)(Qh + ((size_t)h * V + q0 + r) * HD + qq * 16);
        const uint4* s2 = (const uint4*)(Ql + ((size_t)h * V + q0 + r) * HD + qq * 16);
        *(uint4*)(sm + r * 80 + qq * 32) = s1[0];
        *(uint4*)(sm + r * 80 + qq * 32 + 16) = s1[1];
        *(uint4*)(sm + 10240 + r * 80 + qq * 32) = s2[0];
        *(uint4*)(sm + 10240 + r * 80 + qq * 32 + 16) = s2[1];
    }
    __syncthreads();
    uint32_t qfh[2][2][4], qfl[2][2][4];
    #pragma unroll
    for (int mf = 0; mf < 2; mf++)
        #pragma unroll
        for (int kk = 0; kk < 2; kk++) {
            uint32_t ad = smb + (wm * 32 + mf * 16 + a_ro) * 80 + (kk * 16 + a_co) * 2;
            ldsm4(qfh[mf][kk], ad);
            ldsm4(qfl[mf][kk], ad + 10240);
        }
    __syncthreads();

    float oacc[2][4][4];
    #pragma unroll
    for (int a = 0; a < 2; a++)
        #pragma unroll
        for (int b = 0; b < 4; b++)
            #pragma unroll
            for (int c = 0; c < 4; c++) oacc[a][b][c] = 0.0f;
    float rs[2][2] = {{0.0f, 0.0f}, {0.0f, 0.0f}};

    for (int kt = zb * 16; kt < zb * 16 + 16; kt++) {
        {
            int r = tid >> 1, qq = tid & 1;
            const uint4* s1 = (const uint4*)(Kh + ((size_t)h * V + kt * 128 + r) * HD + qq * 16);
            const uint4* s2 = (const uint4*)(Kl + ((size_t)h * V + kt * 128 + r) * HD + qq * 16);
            *(uint4*)(sm + r * 80 + qq * 32) = s1[0];
            *(uint4*)(sm + r * 80 + qq * 32 + 16) = s1[1];
            *(uint4*)(sm + 10240 + r * 80 + qq * 32) = s2[0];
            *(uint4*)(sm + 10240 + r * 80 + qq * 32 + 16) = s2[1];
            int r2 = tid >> 3, q2 = tid & 7;
            const uint4* s3 = (const uint4*)(Vth + ((size_t)h * HD + r2) * V + kt * 128 + q2 * 16);
            const uint4* s4 = (const uint4*)(Vtl + ((size_t)h * HD + r2) * V + kt * 128 + q2 * 16);
            *(uint4*)(sm + 20480 + r2 * 272 + q2 * 32) = s3[0];
            *(uint4*)(sm + 20480 + r2 * 272 + q2 * 32 + 16) = s3[1];
            *(uint4*)(sm + 29184 + r2 * 272 + q2 * 32) = s4[0];
            *(uint4*)(sm + 29184 + r2 * 272 + q2 * 32 + 16) = s4[1];
        }
        __syncthreads();

        float sacc[2][8][4];
        #pragma unroll
        for (int a = 0; a < 2; a++)
            #pragma unroll
            for (int b = 0; b < 8; b++)
                #pragma unroll
                for (int c = 0; c < 4; c++) sacc[a][b][c] = 0.0f;
        #pragma unroll
        for (int kk = 0; kk < 2; kk++) {
            uint32_t bh[8][2], bl[8][2], t[4];
            #pragma unroll
            for (int nf2 = 0; nf2 < 4; nf2++) {
                uint32_t bd = smb + (wn * 64 + nf2 * 16 + b_ro) * 80 + (kk * 16 + b_co) * 2;
                ldsm4(t, bd);
                bh[2*nf2][0] = t[0]; bh[2*nf2][1] = t[1];
                bh[2*nf2+1][0] = t[2]; bh[2*nf2+1][1] = t[3];
                ldsm4(t, bd + 10240);
                bl[2*nf2][0] = t[0]; bl[2*nf2][1] = t[1];
                bl[2*nf2+1][0] = t[2]; bl[2*nf2+1][1] = t[3];
            }
            #pragma unroll
            for (int mf = 0; mf < 2; mf++)
                #pragma unroll
                for (int nf = 0; nf < 8; nf++) {
                    mma_bf16(sacc[mf][nf], qfh[mf][kk], bh[nf]);
                    mma_bf16(sacc[mf][nf], qfl[mf][kk], bh[nf]);
                    mma_bf16(sacc[mf][nf], qfh[mf][kk], bl[nf]);
                }
        }
        #pragma unroll
        for (int mf = 0; mf < 2; mf++)
            #pragma unroll
            for (int nf = 0; nf < 8; nf++) {
                float* c = sacc[mf][nf];
                c[0] = __expf(c[0]); c[1] = __expf(c[1]);
                c[2] = __expf(c[2]); c[3] = __expf(c[3]);
                rs[mf][0] += c[0] + c[1];
                rs[mf][1] += c[2] + c[3];
            }
        #pragma unroll
        for (int j2 = 0; j2 < 4; j2++) {
            uint32_t vbh[4][2], vbl[4][2], t[4];
            #pragma unroll
            for (int nf2 = 0; nf2 < 2; nf2++) {
                uint32_t bd = smb + 20480 + (nf2 * 16 + b_ro) * 272 + (wn * 64 + j2 * 16 + b_co) * 2;
                ldsm4(t, bd);
                vbh[2*nf2][0] = t[0]; vbh[2*nf2][1] = t[1];
                vbh[2*nf2+1][0] = t[2]; vbh[2*nf2+1][1] = t[3];
                ldsm4(t, bd + 8704);
                vbl[2*nf2][0] = t[0]; vbl[2*nf2][1] = t[1];
                vbl[2*nf2+1][0] = t[2]; vbl[2*nf2+1][1] = t[3];
            }
            #pragma unroll
            for (int mf = 0; mf < 2; mf++) {
                const float* p0 = sacc[mf][2 * j2];
                const float* p1 = sacc[mf][2 * j2 + 1];
                uint32_t ah[4], al[4];
                ah[0] = pack_bf(p0[0], p0[1]); al[0] = pack_lo(p0[0], p0[1]);
                ah[1] = pack_bf(p0[2], p0[3]); al[1] = pack_lo(p0[2], p0[3]);
                ah[2] = pack_bf(p1[0], p1[1]); al[2] = pack_lo(p1[0], p1[1]);
                ah[3] = pack_bf(p1[2], p1[3]); al[3] = pack_lo(p1[2], p1[3]);
                #pragma unroll
                for (int nf = 0; nf < 4; nf++) {
                    mma_bf16(oacc[mf][nf], ah, vbh[nf]);
                    mma_bf16(oacc[mf][nf], al, vbh[nf]);
                    mma_bf16(oacc[mf][nf], ah, vbl[nf]);
                }
            }
        }
        __syncthreads();
    }

    float* rsb = (float*)(sm + 37888);
    #pragma unroll
    for (int mf = 0; mf < 2; mf++)
        #pragma unroll
        for (int i = 0; i < 2; i++) {
            float v = rs[mf][i];
            v += __shfl_xor_sync(0xFFFFFFFF, v, 1);
            v += __shfl_xor_sync(0xFFFFFFFF, v, 2);
            rs[mf][i] = v;
        }
    if (tg == 0) {
        #pragma unroll
        for (int mf = 0; mf < 2; mf++) {
            rsb[wn * 128 + wm * 32 + mf * 16 + g] = rs[mf][0];
            rsb[wn * 128 + wm * 32 + mf * 16 + g + 8] = rs[mf][1];
        }
    }
    float* Osm = (float*)sm;
    __syncthreads();
    if (wn == 1) {
        #pragma unroll
        for (int mf = 0; mf < 2; mf++)
            #pragma unroll
            for (int nf = 0; nf < 4; nf++) {
                int row = wm * 32 + mf * 16 + g, col = nf * 8 + tg * 2;
                Osm[row * 34 + col] = oacc[mf][nf][0];
                Osm[row * 34 + col + 1] = oacc[mf][nf][1];
                Osm[(row + 8) * 34 + col] = oacc[mf][nf][2];
                Osm[(row + 8) * 34 + col + 1] = oacc[mf][nf][3];
            }
    }
    __syncthreads();
    if (wn == 0) {
        size_t base = (size_t)(h * 2 + zb) * V + q0;
        #pragma unroll
        for (int mf = 0; mf < 2; mf++) {
            int row = wm * 32 + mf * 16 + g;
            if (tg == 0) {
                lpart[base + row] = rsb[row] + rsb[128 + row];
                lpart[base + row + 8] = rsb[row + 8] + rsb[128 + row + 8];
            }
            #pragma unroll
            for (int nf = 0; nf < 4; nf++) {
                int col = nf * 8 + tg * 2;
                float2 v0 = make_float2(oacc[mf][nf][0] + Osm[row * 34 + col],
                                        oacc[mf][nf][1] + Osm[row * 34 + col + 1]);
                float2 v1 = make_float2(oacc[mf][nf][2] + Osm[(row + 8) * 34 + col],
                                        oacc[mf][nf][3] + Osm[(row + 8) * 34 + col + 1]);
                *(float2*)&opart[(base + row) * 32 + col] = v0;
                *(float2*)&opart[(base + row + 8) * 32 + col] = v1;
            }
        }
    }
}

// ===================== host orchestration ===================================
extern "C" void kernel_launch(void* const* d_in, const int* in_sizes, int n_in,
                              void* d_out, int out_size)
{
    const int*   visits  = (const int*)d_in[0];
    const float* X_hyp   = (const float*)d_in[1];
    const float* kernels = (const float*)d_in[2];
    const float* proj_W  = (const float*)d_in[3];
    const float* proj_b  = (const float*)d_in[4];
    const float* Wqkv    = (const float*)d_in[5];
    const float* bqkv    = (const float*)d_in[6];
    const float* Wo      = (const float*)d_in[7];
    const float* bo      = (const float*)d_in[8];
    const float* W1      = (const float*)d_in[9];
    const float* b1      = (const float*)d_in[10];
    const float* W2      = (const float*)d_in[11];
    const float* b2      = (const float*)d_in[12];
    const float* ln1_g   = (const float*)d_in[13];
    const float* ln1_b   = (const float*)d_in[14];
    const float* ln2_g   = (const float*)d_in[15];
    const float* ln2_b   = (const float*)d_in[16];
    float* out = (float*)d_out;

    float *pZ0, *pYt, *pPart, *pX, *pqkv, *pattn, *pff, *pop, *plp;
    __nv_bfloat16 *pQh, *pQl, *pKh, *pKl, *pVh, *pVl;
    cudaGetSymbolAddress((void**)&pZ0, g_Z0);
    cudaGetSymbolAddress((void**)&pYt, g_Yt);
    cudaGetSymbolAddress((void**)&pPart, g_part);
    cudaGetSymbolAddress((void**)&pX, g_X);
    cudaGetSymbolAddress((void**)&pqkv, g_qkv);
    cudaGetSymbolAddress((void**)&pattn, g_attn);
    cudaGetSymbolAddress((void**)&pff, g_ff);
    cudaGetSymbolAddress((void**)&pop, g_opart);
    cudaGetSymbolAddress((void**)&plp, g_lpart);
    cudaGetSymbolAddress((void**)&pQh, g_Qh);
    cudaGetSymbolAddress((void**)&pQl, g_Ql);
    cudaGetSymbolAddress((void**)&pKh, g_KBh);
    cudaGetSymbolAddress((void**)&pKl, g_KBl);
    cudaGetSymbolAddress((void**)&pVh, g_Vh);
    cudaGetSymbolAddress((void**)&pVl, g_Vl);

    k_logmap0<<<V, 128>>>(X_hyp, pZ0);

    k_mm<<<dim3(1, 32, 3), 256>>>(proj_W, KS * D, 128,
                                  pZ0, D, 0,
                                  pYt, V, (long)D * V,
                                  1, 128, nullptr, nullptr, 0, nullptr, nullptr);

    k_mm<<<dim3(32, 1, 12), 256>>>(kernels, V, (long)V * V,
                                   pYt, V, (long)D * V,
                                   pPart, D, (long)V * D,
                                   4, 1024, nullptr, nullptr, 0, nullptr, nullptr);
    k_reduce12<<<V, 128>>>(pPart, proj_b, pX);

    for (int l = 0; l < NL; l++) {
        k_mm<<<dim3(32, 3, 1), 256>>>(pX, D, 0,
                                      Wqkv + (size_t)l * 3 * D * D, D, 0,
                                      pqkv, 3 * D, 0, 1, 128,
                                      bqkv + l * 3 * D, nullptr, 0, nullptr, nullptr);

        k_prep_qk<<<2048, 256>>>(pqkv, pQh, pQl, pKh, pKl);
        k_prep_v<<<2048, 256>>>(pqkv, pVh, pVl);
        k_flash<<<dim3(32, NH, 2), 256>>>(pQh, pQl, pKh, pKl, pVh, pVl, pop, plp);
        k_comb2<<<V, 128>>>(pop, plp, pattn);

        // X = LN1(X + attn @ Wo^T + bo)   (fused LN epilogue, in-place X)
        k_mm<<<dim3(32, 1, 1), 256>>>(pattn, D, 0,
                                      Wo + (size_t)l * D * D, D, 0,
                                      pX, D, 0, 1, 128,
                                      bo + l * D, pX, 0,
                                      ln1_g + l * D, ln1_b + l * D);

        k_mm<<<dim3(32, 1, 1), 256>>>(pX, D, 0,
                                      W1 + (size_t)l * FF * D, D, 0,
                                      pff, FF, 0, 1, 128,
                                      b1 + l * FF, nullptr, 1, nullptr, nullptr);

        // X = LN2(X + ff @ W2^T + b2)
        k_mm<<<dim3(32, 1, 1), 256>>>(pff, FF, 0,
                                      W2 + (size_t)l * D * FF, FF, 0,
                                      pX, D, 0, 1, 128,
                                      b2 + l * D, pX, 0,
                                      ln2_g + l * D, ln2_b + l * D);
    }

    k_pool<<<NVIS, 128>>>(visits, pX, out);
}